// round 3
// baseline (speedup 1.0000x reference)
#include <cuda_runtime.h>
#include <cstdint>
#include <math.h>

// ---------------- problem constants ----------------
#define BQ     32
#define LQ     128
#define HQ     200
#define MROWS  4096          // L*B rows, row m = t*32 + b
#define IND    550
#define KP0    560           // padded K for layer0 A
#define K1     400
#define NG     800           // 4*H gates
#define XGP    832           // padded gate stride (13 * 64)
#define NPAIR  8001
#define SPAN_BSTRIDE (NPAIR*400)          // 3,200,400
#define SPAN_TOTAL   (BQ*NPAIR*400)       // 102,412,800
#define PREC   50            // CTAs per direction in recurrent kernel

// ---------------- device scratch (no runtime allocation) ----------------
__device__ float g_x0[MROWS * KP0];          // embedded input, zero-padded K
__device__ float g_xg[2 * MROWS * XGP];      // gate pre-activations (reused both layers)
__device__ float g_h0[MROWS * 400];          // layer0 output  [t*32+b][dir*200+c]
__device__ float g_h1[MROWS * 400];          // layer1 output
__device__ unsigned g_bar0[2 * LQ];          // step barriers layer0 [dir][step]
__device__ unsigned g_bar1[2 * LQ];          // step barriers layer1

// ---------------- helpers ----------------
__device__ __forceinline__ float sigf(float x) { return 1.0f / (1.0f + __expf(-x)); }

__device__ __forceinline__ uint32_t f2tf32(float x) {
    uint32_t r;
    asm("cvt.rna.tf32.f32 %0, %1;" : "=r"(r) : "f"(x));
    return r;
}

// =====================================================================
// Kernel 1: embedding gather (also zeroes the step barriers each launch)
// =====================================================================
__global__ void __launch_bounds__(256) emb_kernel(
    const int* __restrict__ lang, const int* __restrict__ word,
    const int* __restrict__ pos,  const int* __restrict__ dep,
    const int* __restrict__ ent,  const int* __restrict__ iob,
    const float* __restrict__ El, const float* __restrict__ Ew,
    const float* __restrict__ Ep, const float* __restrict__ Ed,
    const float* __restrict__ Ee, const float* __restrict__ Ei)
{
    int m = blockIdx.x;                 // t*32 + b
    int t = m >> 5, b = m & 31;
    int tid = threadIdx.x;

    if (m == 0 && tid < 256) { g_bar0[tid] = 0u; g_bar1[tid] = 0u; }

    int li = lang[b * LQ + t];
    int wi = word[b * LQ + t];
    int pi = pos[b * LQ + t];
    int di = dep[b * LQ + t];
    int ei = ent[b * LQ + t];
    int ii = iob[b * LQ + t];

    float* dst = g_x0 + (size_t)m * KP0;
    for (int c = tid; c < KP0; c += 256) {
        float v;
        if      (c < 50)  v = El[li * 50  + c];
        else if (c < 350) v = Ew[wi * 300 + (c - 50)];
        else if (c < 400) v = Ep[pi * 50  + (c - 350)];
        else if (c < 450) v = Ed[di * 50  + (c - 400)];
        else if (c < 500) v = Ee[ei * 50  + (c - 450)];
        else if (c < 550) v = Ei[ii * 50  + (c - 500)];
        else              v = 0.0f;     // K padding for the tf32 GEMM
        dst[c] = v;
    }
}

// =====================================================================
// Kernel 2: xg GEMM  C[m][n] = A[m][:K] . W[dir][n][:K] + bi[n] + bh[n]
// tf32 mma.sync m16n8k8; CTA tile 128x64, 8 warps (4x2), warp tile 32x32.
// LAYER selects A (g_x0 / g_h0) and K at compile time.
// =====================================================================
template<int LAYER>
__global__ void __launch_bounds__(256) xg_gemm(
    const float* __restrict__ W, const float* __restrict__ bi,
    const float* __restrict__ bh)
{
    constexpr int K   = (LAYER == 0) ? IND : K1;
    constexpr int KPA = (LAYER == 0) ? KP0 : K1;
    const float* A = (LAYER == 0) ? g_x0 : g_h0;

    __shared__ uint32_t As[128 * 20];   // [m][k] padded to 20 (conflict-free)
    __shared__ uint32_t Bs[64 * 20];    // [n][k] padded to 20

    int mt0 = blockIdx.x * 128;
    int nt0 = blockIdx.y * 64;
    int dir = blockIdx.z;
    const float* Wd  = W  + (size_t)dir * NG * K;
    const float* bid = bi + dir * NG;
    const float* bhd = bh + dir * NG;
    float* Cd = g_xg + (size_t)dir * MROWS * XGP;

    int tid  = threadIdx.x;
    int w    = tid >> 5, lane = tid & 31;
    int wm   = w & 3,  wn = w >> 2;          // 4 x 2 warp grid
    int gr   = lane >> 2, lc = lane & 3;

    float acc[2][4][4];
#pragma unroll
    for (int a = 0; a < 2; a++)
#pragma unroll
        for (int b2 = 0; b2 < 4; b2++)
#pragma unroll
            for (int c = 0; c < 4; c++) acc[a][b2][c] = 0.0f;

    const int KIT = KPA / 16;
    for (int kt = 0; kt < KIT; kt++) {
        int kbase = kt * 16;
        // ---- global -> smem A (128x16), 2 float4 per thread, cvt to tf32 ----
#pragma unroll
        for (int r = 0; r < 2; r++) {
            int q   = tid + r * 256;
            int row = q >> 2, c4 = (q & 3) * 4;
            float4 v = *(const float4*)(A + (size_t)(mt0 + row) * KPA + kbase + c4);
            uint32_t* d = As + row * 20 + c4;
            d[0] = f2tf32(v.x); d[1] = f2tf32(v.y);
            d[2] = f2tf32(v.z); d[3] = f2tf32(v.w);
        }
        // ---- global -> smem B (64x16), scalar guarded loads ----
#pragma unroll
        for (int r = 0; r < 4; r++) {
            int e = tid + r * 256;
            int n = e >> 4, k = e & 15;
            int ng = nt0 + n, gk = kbase + k;
            float v = (ng < NG && gk < K) ? Wd[(size_t)ng * K + gk] : 0.0f;
            Bs[n * 20 + k] = f2tf32(v);
        }
        __syncthreads();

#pragma unroll
        for (int kk = 0; kk < 16; kk += 8) {
            uint32_t af[2][4], bf[4][2];
#pragma unroll
            for (int mt = 0; mt < 2; mt++) {
                int rb = wm * 32 + mt * 16 + gr;
                af[mt][0] = As[rb * 20 + kk + lc];
                af[mt][1] = As[(rb + 8) * 20 + kk + lc];
                af[mt][2] = As[rb * 20 + kk + lc + 4];
                af[mt][3] = As[(rb + 8) * 20 + kk + lc + 4];
            }
#pragma unroll
            for (int nt = 0; nt < 4; nt++) {
                int nb = wn * 32 + nt * 8 + gr;
                bf[nt][0] = Bs[nb * 20 + kk + lc];
                bf[nt][1] = Bs[nb * 20 + kk + lc + 4];
            }
#pragma unroll
            for (int mt = 0; mt < 2; mt++)
#pragma unroll
                for (int nt = 0; nt < 4; nt++) {
                    asm volatile(
                        "mma.sync.aligned.m16n8k8.row.col.f32.tf32.tf32.f32 "
                        "{%0,%1,%2,%3}, {%4,%5,%6,%7}, {%8,%9}, {%0,%1,%2,%3};"
                        : "+f"(acc[mt][nt][0]), "+f"(acc[mt][nt][1]),
                          "+f"(acc[mt][nt][2]), "+f"(acc[mt][nt][3])
                        : "r"(af[mt][0]), "r"(af[mt][1]), "r"(af[mt][2]), "r"(af[mt][3]),
                          "r"(bf[nt][0]), "r"(bf[nt][1]));
                }
        }
        __syncthreads();
    }

    // ---- epilogue: add (bi+bh), write padded xg ----
#pragma unroll
    for (int mt = 0; mt < 2; mt++) {
        int row0 = mt0 + wm * 32 + mt * 16 + gr;
#pragma unroll
        for (int nt = 0; nt < 4; nt++) {
            int col = nt0 + wn * 32 + nt * 8 + 2 * lc;
            if (col < NG) {
                float bs0 = bid[col] + bhd[col];
                float bs1 = bid[col + 1] + bhd[col + 1];
                Cd[(size_t)row0 * XGP + col]           = acc[mt][nt][0] + bs0;
                Cd[(size_t)row0 * XGP + col + 1]       = acc[mt][nt][1] + bs1;
                Cd[(size_t)(row0 + 8) * XGP + col]     = acc[mt][nt][2] + bs0;
                Cd[(size_t)(row0 + 8) * XGP + col + 1] = acc[mt][nt][3] + bs1;
            }
        }
    }
}

// =====================================================================
// Kernel 3: persistent BiLSTM recurrence for one layer.
// Grid = 100 CTAs: dir = cta/50, slice = cta%50 owns h-columns [4c0,4c0+4)
// and all 4 gates for them (16 Whh rows resident in smem).
// Step sync: per-(dir,step) release/acquire counters in global memory.
// =====================================================================
template<int LAYER>
__global__ void __launch_bounds__(256) lstm_rec(const float* __restrict__ Whh)
{
    float* hout   = (LAYER == 0) ? g_h0  : g_h1;
    unsigned* bar = (LAYER == 0) ? g_bar0 : g_bar1;

    __shared__ float ws[16 * 200];   // Whh slice [row_local][k]
    __shared__ float hs[32 * 212];   // h_prev [batch][k], pad 212 -> conflict-free
    __shared__ float gs[16 * 32];    // gate partials [row_local][batch]
    __shared__ float cs[4 * 32];     // cell state [col_local][batch]

    int cta   = blockIdx.x;
    int dir   = cta / PREC;
    int slice = cta % PREC;
    int c0    = slice * 4;
    int tid   = threadIdx.x;
    const bool fwd = (dir == 0);

    const float* xgd = g_xg + (size_t)dir * MROWS * XGP;
    const float* Wd  = Whh + (size_t)dir * NG * HQ;
    unsigned* bard   = bar + dir * LQ;

    // load Whh slice: row_local r -> global row (r>>2)*200 + c0 + (r&3)
    for (int e = tid; e < 16 * 200; e += 256) {
        int r = e / 200, k = e % 200;
        int rg = (r >> 2) * 200 + c0 + (r & 3);
        ws[r * 200 + k] = Wd[(size_t)rg * HQ + k];
    }
    if (tid < 128) cs[tid] = 0.0f;
    __syncthreads();

    int w = tid >> 5, lane = tid & 31;
    int b = lane;
    int r0 = 2 * w, r1 = 2 * w + 1;
    int rg0 = (r0 >> 2) * 200 + c0 + (r0 & 3);
    int rg1 = (r1 >> 2) * 200 + c0 + (r1 & 3);

    for (int s = 0; s < LQ; s++) {
        int t = fwd ? s : (LQ - 1 - s);

        // prefetch xg before waiting on the barrier (independent of h)
        float xv0 = xgd[(size_t)(t * 32 + b) * XGP + rg0];
        float xv1 = xgd[(size_t)(t * 32 + b) * XGP + rg1];

        if (s > 0) {
            if (tid == 0) {
                unsigned v;
                do {
                    asm volatile("ld.acquire.gpu.global.u32 %0, [%1];"
                                 : "=r"(v) : "l"(bard + (s - 1)) : "memory");
                } while (v < (unsigned)PREC);
            }
            __syncthreads();
            int tp = fwd ? (t - 1) : (t + 1);
            for (int i = tid; i < 32 * 50; i += 256) {
                int bb = i / 50, q = i % 50;
                float4 v = *(const float4*)(hout + (size_t)(tp * 32 + bb) * 400
                                            + dir * 200 + q * 4);
                *(float4*)(hs + bb * 212 + q * 4) = v;
            }
        } else {
            for (int i = tid; i < 32 * 212; i += 256) hs[i] = 0.0f;
        }
        __syncthreads();

        // dot: gate rows r0,r1 for batch b
        float acc0 = 0.0f, acc1 = 0.0f;
        const float4* h4  = (const float4*)(hs + b * 212);
        const float4* w40 = (const float4*)(ws + r0 * 200);
        const float4* w41 = (const float4*)(ws + r1 * 200);
#pragma unroll 10
        for (int q = 0; q < 50; q++) {
            float4 hv = h4[q];
            float4 wa = w40[q];
            float4 wb = w41[q];
            acc0 = fmaf(hv.x, wa.x, acc0); acc0 = fmaf(hv.y, wa.y, acc0);
            acc0 = fmaf(hv.z, wa.z, acc0); acc0 = fmaf(hv.w, wa.w, acc0);
            acc1 = fmaf(hv.x, wb.x, acc1); acc1 = fmaf(hv.y, wb.y, acc1);
            acc1 = fmaf(hv.z, wb.z, acc1); acc1 = fmaf(hv.w, wb.w, acc1);
        }
        gs[r0 * 32 + b] = xv0 + acc0;
        gs[r1 * 32 + b] = xv1 + acc1;
        __syncthreads();

        // activations + state update (4 cols x 32 batches = 128 threads)
        if (tid < 128) {
            int cl = tid >> 5, bb = tid & 31;
            float gi = gs[(0 + cl) * 32 + bb];
            float gf = gs[(4 + cl) * 32 + bb];
            float gg = gs[(8 + cl) * 32 + bb];
            float go = gs[(12 + cl) * 32 + bb];
            float cnew = sigf(gf) * cs[cl * 32 + bb] + sigf(gi) * tanhf(gg);
            cs[cl * 32 + bb] = cnew;
            float hnew = sigf(go) * tanhf(cnew);
            hout[(size_t)(t * 32 + bb) * 400 + dir * 200 + c0 + cl] = hnew;
        }
        __syncthreads();

        if (tid == 0) {
            asm volatile("red.release.gpu.global.add.u32 [%0], %1;"
                         :: "l"(bard + s), "r"(1u) : "memory");
        }
    }
}

// =====================================================================
// Kernel 4: span features
// out[b][p][c] (c<200):  h1[bidx][c]   - h1[aidx][c]          (fwd diff)
//             (c>=200):  h1[a+1][c]    - h1[b+1][c]           (bwd diff)
// one block per pair p (8001 blocks)
// =====================================================================
__global__ void __launch_bounds__(256) span_kernel(float* __restrict__ out)
{
    int p = blockIdx.x;
    // invert p -> (a, b) on the strict upper triangle of 127x127
    int a = (int)((253.0 - sqrt(64009.0 - 8.0 * (double)p)) * 0.5);
    if (a < 0) a = 0; if (a > 125) a = 125;
    while (a > 0 && (a * (253 - a)) / 2 > p) a--;
    while (((a + 1) * (252 - a)) / 2 <= p) a++;
    int bpos = a + 1 + (p - (a * (253 - a)) / 2);

    const float* h1 = g_h1;
    for (int i = threadIdx.x; i < 32 * 100; i += 256) {
        int batch = i / 100, q = i % 100;
        int c = q * 4;
        int rhi, rlo;
        if (q < 50) { rhi = bpos * 32 + batch;      rlo = a * 32 + batch; }
        else        { rhi = (a + 1) * 32 + batch;   rlo = (bpos + 1) * 32 + batch; }
        float4 vh = *(const float4*)(h1 + (size_t)rhi * 400 + c);
        float4 vl = *(const float4*)(h1 + (size_t)rlo * 400 + c);
        float4 r;
        r.x = vh.x - vl.x; r.y = vh.y - vl.y;
        r.z = vh.z - vl.z; r.w = vh.w - vl.w;
        *(float4*)(out + (size_t)batch * SPAN_BSTRIDE + (size_t)p * 400 + c) = r;
    }
}

// =====================================================================
// Kernel 5: sentence lengths - 2 (second tuple output, cast to float)
// =====================================================================
__global__ void lens_kernel(const int* __restrict__ word, float* __restrict__ out)
{
    int b = threadIdx.x;
    if (b < BQ) {
        int cnt = 0;
        for (int l = 0; l < LQ; l++) cnt += (word[b * LQ + l] != 0);
        out[SPAN_TOTAL + b] = (float)(cnt - 2);
    }
}

// =====================================================================
// launcher
// =====================================================================
extern "C" void kernel_launch(void* const* d_in, const int* in_sizes, int n_in,
                              void* d_out, int out_size)
{
    const int*   lang  = (const int*)d_in[0];
    const int*   word  = (const int*)d_in[1];
    const int*   pos   = (const int*)d_in[2];
    const int*   dep   = (const int*)d_in[3];
    const int*   ent   = (const int*)d_in[4];
    const int*   iob   = (const int*)d_in[5];
    const float* El    = (const float*)d_in[6];
    const float* Ew    = (const float*)d_in[7];
    const float* Ep    = (const float*)d_in[8];
    const float* Ed    = (const float*)d_in[9];
    const float* Ee    = (const float*)d_in[10];
    const float* Ei    = (const float*)d_in[11];
    const float* Wih0  = (const float*)d_in[12];
    const float* Whh0  = (const float*)d_in[13];
    const float* bih0  = (const float*)d_in[14];
    const float* bhh0  = (const float*)d_in[15];
    const float* Wih1  = (const float*)d_in[16];
    const float* Whh1  = (const float*)d_in[17];
    const float* bih1  = (const float*)d_in[18];
    const float* bhh1  = (const float*)d_in[19];
    float* out = (float*)d_out;

    emb_kernel<<<MROWS, 256>>>(lang, word, pos, dep, ent, iob, El, Ew, Ep, Ed, Ee, Ei);
    xg_gemm<0><<<dim3(32, 13, 2), 256>>>(Wih0, bih0, bhh0);
    lstm_rec<0><<<2 * PREC, 256>>>(Whh0);
    xg_gemm<1><<<dim3(32, 13, 2), 256>>>(Wih1, bih1, bhh1);
    lstm_rec<1><<<2 * PREC, 256>>>(Whh1);
    span_kernel<<<NPAIR, 256>>>(out);
    if (out_size >= SPAN_TOTAL + BQ) {
        lens_kernel<<<1, 32>>>(word, out);
    }
}

// round 4
// speedup vs baseline: 1.0078x; 1.0078x over previous
#include <cuda_runtime.h>
#include <cstdint>
#include <math.h>

// ---------------- problem constants ----------------
#define BQ     32
#define LQ     128
#define HQ     200
#define MROWS  4096          // L*B rows, row m = t*32 + b
#define IND    550
#define KP0    560           // padded K for layer0 A
#define K1     400
#define NG     800           // 4*H gates
#define XGP    832           // padded gate stride (13 * 64)
#define NPAIR  8001
#define SPAN_BSTRIDE (NPAIR*400)          // 3,200,400
#define SPAN_TOTAL   (BQ*NPAIR*400)       // 102,412,800
#define PREC   50            // CTAs per direction in recurrent kernel

// ---------------- device scratch (no runtime allocation) ----------------
__device__ float g_x0[MROWS * KP0];          // embedded input, zero-padded K
__device__ float g_xg[2 * MROWS * XGP];      // gate pre-activations (reused both layers)
__device__ float g_h0[MROWS * 400];          // layer0 output  [t*32+b][dir*200+c]
__device__ float g_h1[MROWS * 400];          // layer1 output
__device__ unsigned g_bar0[2 * LQ];          // step barriers layer0 [dir][step]
__device__ unsigned g_bar1[2 * LQ];          // step barriers layer1

// ---------------- helpers ----------------
__device__ __forceinline__ float sigf(float x) { return 1.0f / (1.0f + __expf(-x)); }

__device__ __forceinline__ uint32_t f2tf32(float x) {
    uint32_t r;
    asm("cvt.rna.tf32.f32 %0, %1;" : "=r"(r) : "f"(x));
    return r;
}

// =====================================================================
// Kernel 1: embedding gather (also zeroes the step barriers each launch)
// =====================================================================
__global__ void __launch_bounds__(256) emb_kernel(
    const int* __restrict__ lang, const int* __restrict__ word,
    const int* __restrict__ pos,  const int* __restrict__ dep,
    const int* __restrict__ ent,  const int* __restrict__ iob,
    const float* __restrict__ El, const float* __restrict__ Ew,
    const float* __restrict__ Ep, const float* __restrict__ Ed,
    const float* __restrict__ Ee, const float* __restrict__ Ei)
{
    int m = blockIdx.x;                 // t*32 + b
    int t = m >> 5, b = m & 31;
    int tid = threadIdx.x;

    if (m == 0 && tid < 256) { g_bar0[tid] = 0u; g_bar1[tid] = 0u; }

    int li = lang[b * LQ + t];
    int wi = word[b * LQ + t];
    int pi = pos[b * LQ + t];
    int di = dep[b * LQ + t];
    int ei = ent[b * LQ + t];
    int ii = iob[b * LQ + t];

    float* dst = g_x0 + (size_t)m * KP0;
    for (int c = tid; c < KP0; c += 256) {
        float v;
        if      (c < 50)  v = El[li * 50  + c];
        else if (c < 350) v = Ew[wi * 300 + (c - 50)];
        else if (c < 400) v = Ep[pi * 50  + (c - 350)];
        else if (c < 450) v = Ed[di * 50  + (c - 400)];
        else if (c < 500) v = Ee[ei * 50  + (c - 450)];
        else if (c < 550) v = Ei[ii * 50  + (c - 500)];
        else              v = 0.0f;     // K padding for the tf32 GEMM
        dst[c] = v;
    }
}

// =====================================================================
// Kernel 2: xg GEMM  C[m][n] = A[m][:K] . W[dir][n][:K] + bi[n] + bh[n]
// tf32 mma.sync m16n8k8; CTA tile 128x64, 8 warps (4x2), warp tile 32x32.
// LAYER selects A (g_x0 / g_h0) and K at compile time.
// =====================================================================
template<int LAYER>
__global__ void __launch_bounds__(256) xg_gemm(
    const float* __restrict__ W, const float* __restrict__ bi,
    const float* __restrict__ bh)
{
    constexpr int K   = (LAYER == 0) ? IND : K1;
    constexpr int KPA = (LAYER == 0) ? KP0 : K1;
    const float* A = (LAYER == 0) ? g_x0 : g_h0;

    __shared__ uint32_t As[128 * 20];   // [m][k] padded to 20 (conflict-free)
    __shared__ uint32_t Bs[64 * 20];    // [n][k] padded to 20

    int mt0 = blockIdx.x * 128;
    int nt0 = blockIdx.y * 64;
    int dir = blockIdx.z;
    const float* Wd  = W  + (size_t)dir * NG * K;
    const float* bid = bi + dir * NG;
    const float* bhd = bh + dir * NG;
    float* Cd = g_xg + (size_t)dir * MROWS * XGP;

    int tid  = threadIdx.x;
    int w    = tid >> 5, lane = tid & 31;
    int wm   = w & 3,  wn = w >> 2;          // 4 x 2 warp grid
    int gr   = lane >> 2, lc = lane & 3;

    float acc[2][4][4];
#pragma unroll
    for (int a = 0; a < 2; a++)
#pragma unroll
        for (int b2 = 0; b2 < 4; b2++)
#pragma unroll
            for (int c = 0; c < 4; c++) acc[a][b2][c] = 0.0f;

    const int KIT = KPA / 16;
    for (int kt = 0; kt < KIT; kt++) {
        int kbase = kt * 16;
        // ---- global -> smem A (128x16), 2 float4 per thread, cvt to tf32 ----
#pragma unroll
        for (int r = 0; r < 2; r++) {
            int q   = tid + r * 256;
            int row = q >> 2, c4 = (q & 3) * 4;
            float4 v = *(const float4*)(A + (size_t)(mt0 + row) * KPA + kbase + c4);
            uint32_t* d = As + row * 20 + c4;
            d[0] = f2tf32(v.x); d[1] = f2tf32(v.y);
            d[2] = f2tf32(v.z); d[3] = f2tf32(v.w);
        }
        // ---- global -> smem B (64x16), scalar guarded loads ----
#pragma unroll
        for (int r = 0; r < 4; r++) {
            int e = tid + r * 256;
            int n = e >> 4, k = e & 15;
            int ng = nt0 + n, gk = kbase + k;
            float v = (ng < NG && gk < K) ? Wd[(size_t)ng * K + gk] : 0.0f;
            Bs[n * 20 + k] = f2tf32(v);
        }
        __syncthreads();

#pragma unroll
        for (int kk = 0; kk < 16; kk += 8) {
            uint32_t af[2][4], bf[4][2];
#pragma unroll
            for (int mt = 0; mt < 2; mt++) {
                int rb = wm * 32 + mt * 16 + gr;
                af[mt][0] = As[rb * 20 + kk + lc];
                af[mt][1] = As[(rb + 8) * 20 + kk + lc];
                af[mt][2] = As[rb * 20 + kk + lc + 4];
                af[mt][3] = As[(rb + 8) * 20 + kk + lc + 4];
            }
#pragma unroll
            for (int nt = 0; nt < 4; nt++) {
                int nb = wn * 32 + nt * 8 + gr;
                bf[nt][0] = Bs[nb * 20 + kk + lc];
                bf[nt][1] = Bs[nb * 20 + kk + lc + 4];
            }
#pragma unroll
            for (int mt = 0; mt < 2; mt++)
#pragma unroll
                for (int nt = 0; nt < 4; nt++) {
                    asm volatile(
                        "mma.sync.aligned.m16n8k8.row.col.f32.tf32.tf32.f32 "
                        "{%0,%1,%2,%3}, {%4,%5,%6,%7}, {%8,%9}, {%0,%1,%2,%3};"
                        : "+f"(acc[mt][nt][0]), "+f"(acc[mt][nt][1]),
                          "+f"(acc[mt][nt][2]), "+f"(acc[mt][nt][3])
                        : "r"(af[mt][0]), "r"(af[mt][1]), "r"(af[mt][2]), "r"(af[mt][3]),
                          "r"(bf[nt][0]), "r"(bf[nt][1]));
                }
        }
        __syncthreads();
    }

    // ---- epilogue: add (bi+bh), write padded xg ----
#pragma unroll
    for (int mt = 0; mt < 2; mt++) {
        int row0 = mt0 + wm * 32 + mt * 16 + gr;
#pragma unroll
        for (int nt = 0; nt < 4; nt++) {
            int col = nt0 + wn * 32 + nt * 8 + 2 * lc;
            if (col < NG) {
                float bs0 = bid[col] + bhd[col];
                float bs1 = bid[col + 1] + bhd[col + 1];
                Cd[(size_t)row0 * XGP + col]           = acc[mt][nt][0] + bs0;
                Cd[(size_t)row0 * XGP + col + 1]       = acc[mt][nt][1] + bs1;
                Cd[(size_t)(row0 + 8) * XGP + col]     = acc[mt][nt][2] + bs0;
                Cd[(size_t)(row0 + 8) * XGP + col + 1] = acc[mt][nt][3] + bs1;
            }
        }
    }
}

// =====================================================================
// Kernel 3: persistent BiLSTM recurrence for one layer.
// Grid = 100 CTAs: dir = cta/50, slice = cta%50 owns h-columns [4c0,4c0+4)
// and all 4 gates for them (16 Whh rows resident in smem).
// Step sync: per-(dir,step) release/acquire counters in global memory.
// =====================================================================
template<int LAYER>
__global__ void __launch_bounds__(256) lstm_rec(const float* __restrict__ Whh)
{
    float* hout   = (LAYER == 0) ? g_h0  : g_h1;
    unsigned* bar = (LAYER == 0) ? g_bar0 : g_bar1;

    __shared__ float ws[16 * 200];   // Whh slice [row_local][k]
    __shared__ float hs[32 * 212];   // h_prev [batch][k], pad 212 -> conflict-free
    __shared__ float gs[16 * 32];    // gate partials [row_local][batch]
    __shared__ float cs[4 * 32];     // cell state [col_local][batch]

    int cta   = blockIdx.x;
    int dir   = cta / PREC;
    int slice = cta % PREC;
    int c0    = slice * 4;
    int tid   = threadIdx.x;
    const bool fwd = (dir == 0);

    const float* xgd = g_xg + (size_t)dir * MROWS * XGP;
    const float* Wd  = Whh + (size_t)dir * NG * HQ;
    unsigned* bard   = bar + dir * LQ;

    // load Whh slice: row_local r -> global row (r>>2)*200 + c0 + (r&3)
    for (int e = tid; e < 16 * 200; e += 256) {
        int r = e / 200, k = e % 200;
        int rg = (r >> 2) * 200 + c0 + (r & 3);
        ws[r * 200 + k] = Wd[(size_t)rg * HQ + k];
    }
    if (tid < 128) cs[tid] = 0.0f;
    __syncthreads();

    int w = tid >> 5, lane = tid & 31;
    int b = lane;
    int r0 = 2 * w, r1 = 2 * w + 1;
    int rg0 = (r0 >> 2) * 200 + c0 + (r0 & 3);
    int rg1 = (r1 >> 2) * 200 + c0 + (r1 & 3);

    for (int s = 0; s < LQ; s++) {
        int t = fwd ? s : (LQ - 1 - s);

        // prefetch xg before waiting on the barrier (independent of h)
        float xv0 = xgd[(size_t)(t * 32 + b) * XGP + rg0];
        float xv1 = xgd[(size_t)(t * 32 + b) * XGP + rg1];

        if (s > 0) {
            if (tid == 0) {
                unsigned v;
                do {
                    asm volatile("ld.acquire.gpu.global.u32 %0, [%1];"
                                 : "=r"(v) : "l"(bard + (s - 1)) : "memory");
                } while (v < (unsigned)PREC);
            }
            __syncthreads();
            int tp = fwd ? (t - 1) : (t + 1);
            for (int i = tid; i < 32 * 50; i += 256) {
                int bb = i / 50, q = i % 50;
                float4 v = *(const float4*)(hout + (size_t)(tp * 32 + bb) * 400
                                            + dir * 200 + q * 4);
                *(float4*)(hs + bb * 212 + q * 4) = v;
            }
        } else {
            for (int i = tid; i < 32 * 212; i += 256) hs[i] = 0.0f;
        }
        __syncthreads();

        // dot: gate rows r0,r1 for batch b
        float acc0 = 0.0f, acc1 = 0.0f;
        const float4* h4  = (const float4*)(hs + b * 212);
        const float4* w40 = (const float4*)(ws + r0 * 200);
        const float4* w41 = (const float4*)(ws + r1 * 200);
#pragma unroll 10
        for (int q = 0; q < 50; q++) {
            float4 hv = h4[q];
            float4 wa = w40[q];
            float4 wb = w41[q];
            acc0 = fmaf(hv.x, wa.x, acc0); acc0 = fmaf(hv.y, wa.y, acc0);
            acc0 = fmaf(hv.z, wa.z, acc0); acc0 = fmaf(hv.w, wa.w, acc0);
            acc1 = fmaf(hv.x, wb.x, acc1); acc1 = fmaf(hv.y, wb.y, acc1);
            acc1 = fmaf(hv.z, wb.z, acc1); acc1 = fmaf(hv.w, wb.w, acc1);
        }
        gs[r0 * 32 + b] = xv0 + acc0;
        gs[r1 * 32 + b] = xv1 + acc1;
        __syncthreads();

        // activations + state update (4 cols x 32 batches = 128 threads)
        if (tid < 128) {
            int cl = tid >> 5, bb = tid & 31;
            float gi = gs[(0 + cl) * 32 + bb];
            float gf = gs[(4 + cl) * 32 + bb];
            float gg = gs[(8 + cl) * 32 + bb];
            float go = gs[(12 + cl) * 32 + bb];
            float cnew = sigf(gf) * cs[cl * 32 + bb] + sigf(gi) * tanhf(gg);
            cs[cl * 32 + bb] = cnew;
            float hnew = sigf(go) * tanhf(cnew);
            hout[(size_t)(t * 32 + bb) * 400 + dir * 200 + c0 + cl] = hnew;
        }
        __syncthreads();

        if (tid == 0) {
            asm volatile("red.release.gpu.global.add.u32 [%0], %1;"
                         :: "l"(bard + s), "r"(1u) : "memory");
        }
    }
}

// =====================================================================
// Kernel 4: span features
// out[b][p][c] (c<200):  h1[bidx][c]   - h1[aidx][c]          (fwd diff)
//             (c>=200):  h1[a+1][c]    - h1[b+1][c]           (bwd diff)
// one block per pair p (8001 blocks)
// =====================================================================
__global__ void __launch_bounds__(256) span_kernel(float* __restrict__ out)
{
    int p = blockIdx.x;
    // invert p -> (a, b) on the strict upper triangle of 127x127
    int a = (int)((253.0 - sqrt(64009.0 - 8.0 * (double)p)) * 0.5);
    if (a < 0) a = 0; if (a > 125) a = 125;
    while (a > 0 && (a * (253 - a)) / 2 > p) a--;
    while (((a + 1) * (252 - a)) / 2 <= p) a++;
    int bpos = a + 1 + (p - (a * (253 - a)) / 2);

    const float* h1 = g_h1;
    for (int i = threadIdx.x; i < 32 * 100; i += 256) {
        int batch = i / 100, q = i % 100;
        int c = q * 4;
        int rhi, rlo;
        if (q < 50) { rhi = bpos * 32 + batch;      rlo = a * 32 + batch; }
        else        { rhi = (a + 1) * 32 + batch;   rlo = (bpos + 1) * 32 + batch; }
        float4 vh = *(const float4*)(h1 + (size_t)rhi * 400 + c);
        float4 vl = *(const float4*)(h1 + (size_t)rlo * 400 + c);
        float4 r;
        r.x = vh.x - vl.x; r.y = vh.y - vl.y;
        r.z = vh.z - vl.z; r.w = vh.w - vl.w;
        *(float4*)(out + (size_t)batch * SPAN_BSTRIDE + (size_t)p * 400 + c) = r;
    }
}

// =====================================================================
// Kernel 5: sentence lengths - 2 (second tuple output, cast to float)
// =====================================================================
__global__ void lens_kernel(const int* __restrict__ word, float* __restrict__ out)
{
    int b = threadIdx.x;
    if (b < BQ) {
        int cnt = 0;
        for (int l = 0; l < LQ; l++) cnt += (word[b * LQ + l] != 0);
        out[SPAN_TOTAL + b] = (float)(cnt - 2);
    }
}

// =====================================================================
// launcher
// =====================================================================
extern "C" void kernel_launch(void* const* d_in, const int* in_sizes, int n_in,
                              void* d_out, int out_size)
{
    const int*   lang  = (const int*)d_in[0];
    const int*   word  = (const int*)d_in[1];
    const int*   pos   = (const int*)d_in[2];
    const int*   dep   = (const int*)d_in[3];
    const int*   ent   = (const int*)d_in[4];
    const int*   iob   = (const int*)d_in[5];
    const float* El    = (const float*)d_in[6];
    const float* Ew    = (const float*)d_in[7];
    const float* Ep    = (const float*)d_in[8];
    const float* Ed    = (const float*)d_in[9];
    const float* Ee    = (const float*)d_in[10];
    const float* Ei    = (const float*)d_in[11];
    const float* Wih0  = (const float*)d_in[12];
    const float* Whh0  = (const float*)d_in[13];
    const float* bih0  = (const float*)d_in[14];
    const float* bhh0  = (const float*)d_in[15];
    const float* Wih1  = (const float*)d_in[16];
    const float* Whh1  = (const float*)d_in[17];
    const float* bih1  = (const float*)d_in[18];
    const float* bhh1  = (const float*)d_in[19];
    float* out = (float*)d_out;

    emb_kernel<<<MROWS, 256>>>(lang, word, pos, dep, ent, iob, El, Ew, Ep, Ed, Ee, Ei);
    xg_gemm<0><<<dim3(32, 13, 2), 256>>>(Wih0, bih0, bhh0);
    lstm_rec<0><<<2 * PREC, 256>>>(Whh0);
    xg_gemm<1><<<dim3(32, 13, 2), 256>>>(Wih1, bih1, bhh1);
    lstm_rec<1><<<2 * PREC, 256>>>(Whh1);
    span_kernel<<<NPAIR, 256>>>(out);
    if (out_size >= SPAN_TOTAL + BQ) {
        lens_kernel<<<1, 32>>>(word, out);
    }
}